// round 3
// baseline (speedup 1.0000x reference)
#include <cuda_runtime.h>
#include <math.h>
#include <stdint.h>

// ---------------------------------------------------------------------------
// QLSTM: T=256, B=256, D=512, H=512.
//   comp  = enc3(relu(enc2(relu(enc1(x)))))              (parallel over T*B)
//   GX    = comp @ gate_w[0:512]  + gate_b               (parallel over T*B)
//   per t: gates = GX[t] + hx @ gate_w[512:1024]
//          f,i,g,o = act(gates) * mask; cx = f*cx + i*g; hx = o*tanh(cx)
// All GEMMs in tf32 mma.sync with fp32 accumulation.
// ---------------------------------------------------------------------------

#define TT      256
#define BBATCH  256
#define DDIM    512
#define HHID    512
#define MROWS   65536            // TT*BBATCH
#define NGATE   2048
#define STATE_SZ (BBATCH*HHID)   // 131072
#define STACKED_SZ ((size_t)TT*BBATCH*HHID)

// Scratch (device globals: allocation-free per harness rules)
__device__ float d_h1[(size_t)MROWS * 128];
__device__ float d_h2[(size_t)MROWS * 64];
__device__ float d_comp[(size_t)MROWS * 512];
__device__ float d_gx[(size_t)MROWS * NGATE];
__device__ float d_hxbuf[2][STATE_SZ];
__device__ float d_cxg[STATE_SZ];
__device__ float d_mask[4];

__device__ __forceinline__ float ftf32(float x) {
    float r; asm("cvt.rna.tf32.f32 %0, %1;" : "=f"(r) : "f"(x)); return r;
}

__device__ __forceinline__ void mma8(float c[4],
                                     uint32_t a0, uint32_t a1, uint32_t a2, uint32_t a3,
                                     uint32_t b0, uint32_t b1) {
    asm volatile(
        "mma.sync.aligned.m16n8k8.row.col.f32.tf32.tf32.f32 "
        "{%0,%1,%2,%3},{%4,%5,%6,%7},{%8,%9},{%0,%1,%2,%3};\n"
        : "+f"(c[0]), "+f"(c[1]), "+f"(c[2]), "+f"(c[3])
        : "r"(a0), "r"(a1), "r"(a2), "r"(a3), "r"(b0), "r"(b1));
}

// ---------------------------------------------------------------------------
// Generic tf32 GEMM: C[M,N] = act(A[M,K] @ B[K,N] + bias), A/B row-major.
// Block tile 64x64, 128 threads (4 warps, warp tile 32x32), KC=32,
// double-buffered smem with register prefetch. Requires M%64==0, N%64==0,
// K%32==0 (all shapes here satisfy this).
// Smem pads: A stride 36 (==4 mod 32), B stride 72 (==8 mod 32) -> no bank
// conflicts on the mma fragment reads.
// ---------------------------------------------------------------------------
template<int RELU>
__global__ void __launch_bounds__(128) gemm_tf32_kernel(
    const float* __restrict__ A, const float* __restrict__ B,
    const float* __restrict__ bias, float* __restrict__ C,
    int M, int N, int K, int ldb)
{
    __shared__ float As[2][2304];   // [64][36]
    __shared__ float Bs[2][2304];   // [32][72]

    const int tid = threadIdx.x;
    const int lane = tid & 31, warp = tid >> 5;
    const int m0 = blockIdx.y * 64, n0 = blockIdx.x * 64;
    const int wm = (warp >> 1) * 32, wn = (warp & 1) * 32;
    const int g = lane >> 2, tg = lane & 3;

    float acc[2][4][4];
#pragma unroll
    for (int i = 0; i < 2; i++)
#pragma unroll
        for (int j = 0; j < 4; j++)
#pragma unroll
            for (int e = 0; e < 4; e++) acc[i][j][e] = 0.f;

    const int NC = K >> 5;
    float4 ra[4], rb[4];

    auto loadg = [&](int kc) {
#pragma unroll
        for (int p = 0; p < 4; p++) {
            int idx = p * 512 + tid * 4;
            int am = idx >> 5, ak = idx & 31;
            ra[p] = *(const float4*)(A + (size_t)(m0 + am) * K + kc + ak);
            int bk = idx >> 6, bn = idx & 63;
            rb[p] = *(const float4*)(B + (size_t)(kc + bk) * ldb + n0 + bn);
        }
    };
    auto store = [&](int buf) {
#pragma unroll
        for (int p = 0; p < 4; p++) {
            int idx = p * 512 + tid * 4;
            int am = idx >> 5, ak = idx & 31;
            float4 v = ra[p];
            v.x = ftf32(v.x); v.y = ftf32(v.y); v.z = ftf32(v.z); v.w = ftf32(v.w);
            *(float4*)&As[buf][am * 36 + ak] = v;
            int bk = idx >> 6, bn = idx & 63;
            float4 w = rb[p];
            w.x = ftf32(w.x); w.y = ftf32(w.y); w.z = ftf32(w.z); w.w = ftf32(w.w);
            *(float4*)&Bs[buf][bk * 72 + bn] = w;
        }
    };
    auto compute = [&](int buf) {
#pragma unroll
        for (int kk = 0; kk < 32; kk += 8) {
            uint32_t a[2][4];
#pragma unroll
            for (int mf = 0; mf < 2; mf++) {
                int rbase = wm + mf * 16 + g;
                a[mf][0] = __float_as_uint(As[buf][rbase * 36 + kk + tg]);
                a[mf][1] = __float_as_uint(As[buf][(rbase + 8) * 36 + kk + tg]);
                a[mf][2] = __float_as_uint(As[buf][rbase * 36 + kk + tg + 4]);
                a[mf][3] = __float_as_uint(As[buf][(rbase + 8) * 36 + kk + tg + 4]);
            }
#pragma unroll
            for (int nf = 0; nf < 4; nf++) {
                uint32_t b0 = __float_as_uint(Bs[buf][(kk + tg) * 72 + wn + nf * 8 + g]);
                uint32_t b1 = __float_as_uint(Bs[buf][(kk + tg + 4) * 72 + wn + nf * 8 + g]);
                mma8(acc[0][nf], a[0][0], a[0][1], a[0][2], a[0][3], b0, b1);
                mma8(acc[1][nf], a[1][0], a[1][1], a[1][2], a[1][3], b0, b1);
            }
        }
    };

    loadg(0);
    store(0);
    __syncthreads();
    for (int c = 0; c < NC; c++) {
        int cur = c & 1;
        if (c + 1 < NC) loadg((c + 1) * 32);
        compute(cur);
        if (c + 1 < NC) store(cur ^ 1);
        __syncthreads();
    }

    // epilogue: bias (+relu), write C
#pragma unroll
    for (int mf = 0; mf < 2; mf++) {
        int r = m0 + wm + mf * 16 + g;
#pragma unroll
        for (int nf = 0; nf < 4; nf++) {
            int col = n0 + wn + nf * 8 + 2 * tg;
            float b0 = bias[col], b1 = bias[col + 1];
            float v0 = acc[mf][nf][0] + b0;
            float v1 = acc[mf][nf][1] + b1;
            float v2 = acc[mf][nf][2] + b0;
            float v3 = acc[mf][nf][3] + b1;
            if (RELU) {
                v0 = fmaxf(v0, 0.f); v1 = fmaxf(v1, 0.f);
                v2 = fmaxf(v2, 0.f); v3 = fmaxf(v3, 0.f);
            }
            float2 p0; p0.x = v0; p0.y = v1;
            float2 p1; p1.x = v2; p1.y = v3;
            *(float2*)(C + (size_t)r * N + col) = p0;
            *(float2*)(C + (size_t)(r + 8) * N + col) = p1;
        }
    }
}

// ---------------------------------------------------------------------------
// Per-timestep fused kernel: gates = GX[t] + hx @ Wh, then LSTM cell.
// Grid: (16 h-tiles of 32) x (8 m-tiles of 32), 256 threads = 8 warps.
// Warp w: gate = w&3, m-half = w>>2 -> computes a 16x32 tile of its gate.
// K=512 looped in KC=32 chunks, double-buffered. Activated gates exchanged
// through smem so each thread can do cx/hx for its (m,h) elements.
// Dynamic smem: As 2*1152 + Bs 2*4352 + gsm 4*1056 = 15232 floats (~60 KB).
// ---------------------------------------------------------------------------
#define LSTM_SMEM_FLOATS 15232

__global__ void __launch_bounds__(256) lstm_step_kernel(
    const float* __restrict__ gate_w, float* __restrict__ out, int t)
{
    extern __shared__ float sm[];
    float* As  = sm;           // 2 * (32*36)
    float* Bs  = sm + 2304;    // 2 * (32*136)
    float* gsm = sm + 11008;   // 4 * (32*33)

    const float* hx_in  = d_hxbuf[t & 1];
    float*       hx_out = d_hxbuf[(t + 1) & 1];
    const float* Wh  = gate_w + (size_t)512 * NGATE;
    const float* gx  = d_gx + (size_t)t * BBATCH * NGATE;
    float*       out_t = out + (size_t)t * BBATCH * HHID;

    const int tid = threadIdx.x;
    const int lane = tid & 31, warp = tid >> 5;
    const int h0 = blockIdx.x * 32, m0 = blockIdx.y * 32;
    const int gate = warp & 3;
    const int mh = (warp >> 2) * 16;
    const int g = lane >> 2, tg = lane & 3;

    float acc[4][4];
#pragma unroll
    for (int j = 0; j < 4; j++)
#pragma unroll
        for (int e = 0; e < 4; e++) acc[j][e] = 0.f;

    float4 ra, rb[4];
    auto loadg = [&](int kc) {
        {
            int idx = tid * 4;
            int am = idx >> 5, ak = idx & 31;
            ra = *(const float4*)(hx_in + (size_t)(m0 + am) * HHID + kc + ak);
        }
#pragma unroll
        for (int p = 0; p < 4; p++) {
            int idx = p * 1024 + tid * 4;
            int bk = idx >> 7, col = idx & 127;
            int bg = col >> 5, j = col & 31;
            rb[p] = *(const float4*)(Wh + (size_t)(kc + bk) * NGATE + bg * 512 + h0 + j);
        }
    };
    auto store = [&](int buf) {
        {
            int idx = tid * 4;
            int am = idx >> 5, ak = idx & 31;
            float4 v = ra;
            v.x = ftf32(v.x); v.y = ftf32(v.y); v.z = ftf32(v.z); v.w = ftf32(v.w);
            *(float4*)&As[buf * 1152 + am * 36 + ak] = v;
        }
#pragma unroll
        for (int p = 0; p < 4; p++) {
            int idx = p * 1024 + tid * 4;
            int bk = idx >> 7, col = idx & 127;
            float4 v = rb[p];
            v.x = ftf32(v.x); v.y = ftf32(v.y); v.z = ftf32(v.z); v.w = ftf32(v.w);
            *(float4*)&Bs[buf * 4352 + bk * 136 + col] = v;
        }
    };
    auto compute = [&](int buf) {
#pragma unroll
        for (int kk = 0; kk < 32; kk += 8) {
            int rbase = mh + g;
            uint32_t a0 = __float_as_uint(As[buf * 1152 + rbase * 36 + kk + tg]);
            uint32_t a1 = __float_as_uint(As[buf * 1152 + (rbase + 8) * 36 + kk + tg]);
            uint32_t a2 = __float_as_uint(As[buf * 1152 + rbase * 36 + kk + tg + 4]);
            uint32_t a3 = __float_as_uint(As[buf * 1152 + (rbase + 8) * 36 + kk + tg + 4]);
#pragma unroll
            for (int nf = 0; nf < 4; nf++) {
                uint32_t b0 = __float_as_uint(Bs[buf * 4352 + (kk + tg) * 136 + gate * 32 + nf * 8 + g]);
                uint32_t b1 = __float_as_uint(Bs[buf * 4352 + (kk + tg + 4) * 136 + gate * 32 + nf * 8 + g]);
                mma8(acc[nf], a0, a1, a2, a3, b0, b1);
            }
        }
    };

    loadg(0);
    store(0);
    __syncthreads();
    const int NC = HHID / 32;   // 16
    for (int c = 0; c < NC; c++) {
        int cur = c & 1;
        if (c + 1 < NC) loadg((c + 1) * 32);
        compute(cur);
        if (c + 1 < NC) store(cur ^ 1);
        __syncthreads();
    }

    // add GX, activate (per-warp gate known), store to smem exchange
    float mk = d_mask[gate];
#pragma unroll
    for (int nf = 0; nf < 4; nf++) {
        int jc = nf * 8 + 2 * tg;
        int r0 = mh + g, r1 = r0 + 8;
        const float* gx0 = gx + (size_t)(m0 + r0) * NGATE + gate * 512 + h0;
        const float* gx1 = gx + (size_t)(m0 + r1) * NGATE + gate * 512 + h0;
        float p0 = acc[nf][0] + gx0[jc];
        float p1 = acc[nf][1] + gx0[jc + 1];
        float p2 = acc[nf][2] + gx1[jc];
        float p3 = acc[nf][3] + gx1[jc + 1];
        float a0, a1, a2, a3;
        if (gate == 2) {
            a0 = tanhf(p0); a1 = tanhf(p1); a2 = tanhf(p2); a3 = tanhf(p3);
        } else {
            a0 = 1.f / (1.f + __expf(-p0));
            a1 = 1.f / (1.f + __expf(-p1));
            a2 = 1.f / (1.f + __expf(-p2));
            a3 = 1.f / (1.f + __expf(-p3));
        }
        gsm[gate * 1056 + r0 * 33 + jc]     = a0 * mk;
        gsm[gate * 1056 + r0 * 33 + jc + 1] = a1 * mk;
        gsm[gate * 1056 + r1 * 33 + jc]     = a2 * mk;
        gsm[gate * 1056 + r1 * 33 + jc + 1] = a3 * mk;
    }
    __syncthreads();

    // LSTM cell update: each thread handles 4 consecutive h for one m row
    int base = tid * 4;
    int lm = base >> 5, lj = base & 31;
#pragma unroll
    for (int q = 0; q < 4; q++) {
        int jj = lj + q;
        float fv = gsm[0 * 1056 + lm * 33 + jj];
        float iv = gsm[1 * 1056 + lm * 33 + jj];
        float gv = gsm[2 * 1056 + lm * 33 + jj];
        float ov = gsm[3 * 1056 + lm * 33 + jj];
        int gi = (m0 + lm) * HHID + h0 + jj;
        float cold = d_cxg[gi];
        float cnew = fv * cold + iv * gv;
        float hn = ov * tanhf(cnew);
        d_cxg[gi] = cnew;
        hx_out[gi] = hn;
        out_t[gi] = hn;
        if (t == TT - 1) {
            out[STACKED_SZ + gi] = hn;
            out[STACKED_SZ + STATE_SZ + gi] = cnew;
        }
    }
}

// ---------------------------------------------------------------------------
__global__ void mask_kernel(const float* __restrict__ w1, const float* __restrict__ b1,
                            const float* __restrict__ w2, const float* __restrict__ b2)
{
    if (threadIdx.x == 0 && blockIdx.x == 0) {
        float h[8];
        for (int j = 0; j < 8; j++) {
            float s = b1[j];
            for (int i = 0; i < 4; i++) s += w1[i * 8 + j];
            h[j] = tanhf(s);
        }
        float o[4], mx = -1e30f;
        for (int k = 0; k < 4; k++) {
            float s = b2[k];
            for (int j = 0; j < 8; j++) s += h[j] * w2[j * 4 + k];
            o[k] = s;
            mx = fmaxf(mx, s);
        }
        float e[4], se = 0.f;
        for (int k = 0; k < 4; k++) { e[k] = expf(o[k] - mx); se += e[k]; }
        for (int k = 0; k < 4; k++) d_mask[k] = e[k] / se;
    }
}

__global__ void init_kernel()
{
    int i = blockIdx.x * blockDim.x + threadIdx.x;
    if (i < STATE_SZ) {
        d_hxbuf[0][i] = 0.f;
        d_cxg[i] = 0.f;
    }
}

// ---------------------------------------------------------------------------
extern "C" void kernel_launch(void* const* d_in, const int* in_sizes, int n_in,
                              void* d_out, int out_size)
{
    (void)in_sizes; (void)n_in; (void)out_size;
    const float* inputs = (const float*)d_in[0];
    const float* ew1 = (const float*)d_in[1];
    const float* eb1 = (const float*)d_in[2];
    const float* ew2 = (const float*)d_in[3];
    const float* eb2 = (const float*)d_in[4];
    const float* ew3 = (const float*)d_in[5];
    const float* eb3 = (const float*)d_in[6];
    const float* gw  = (const float*)d_in[7];
    const float* gb  = (const float*)d_in[8];
    const float* sw1 = (const float*)d_in[9];
    const float* sb1 = (const float*)d_in[10];
    const float* sw2 = (const float*)d_in[11];
    const float* sb2 = (const float*)d_in[12];
    float* out = (float*)d_out;

    void *ph1, *ph2, *pcomp, *pgx;
    cudaGetSymbolAddress(&ph1, d_h1);
    cudaGetSymbolAddress(&ph2, d_h2);
    cudaGetSymbolAddress(&pcomp, d_comp);
    cudaGetSymbolAddress(&pgx, d_gx);

    cudaFuncSetAttribute((const void*)lstm_step_kernel,
                         cudaFuncAttributeMaxDynamicSharedMemorySize,
                         LSTM_SMEM_FLOATS * 4);

    mask_kernel<<<1, 32>>>(sw1, sb1, sw2, sb2);
    init_kernel<<<(STATE_SZ + 255) / 256, 256>>>();

    dim3 tb(128);
    // encoder: h1 = relu(x @ w1 + b1)            [65536,512]x[512,128]
    gemm_tf32_kernel<1><<<dim3(2, MROWS / 64), tb>>>(
        inputs, ew1, eb1, (float*)ph1, MROWS, 128, 512, 128);
    // h2 = relu(h1 @ w2 + b2)                    [65536,128]x[128,64]
    gemm_tf32_kernel<1><<<dim3(1, MROWS / 64), tb>>>(
        (const float*)ph1, ew2, eb2, (float*)ph2, MROWS, 64, 128, 64);
    // comp = h2 @ w3 + b3                        [65536,64]x[64,512]
    gemm_tf32_kernel<0><<<dim3(8, MROWS / 64), tb>>>(
        (const float*)ph2, ew3, eb3, (float*)pcomp, MROWS, 512, 64, 512);
    // GX = comp @ gate_w[0:512] + gate_b         [65536,512]x[512,2048]
    gemm_tf32_kernel<0><<<dim3(32, MROWS / 64), tb>>>(
        (const float*)pcomp, gw, gb, (float*)pgx, MROWS, 2048, 512, 2048);

    // sequential recurrence: 256 small fused GEMM+LSTM kernels
    for (int t = 0; t < TT; t++) {
        lstm_step_kernel<<<dim3(16, 8), 256, LSTM_SMEM_FLOATS * 4>>>(gw, out, t);
    }
}

// round 4
// speedup vs baseline: 1.7601x; 1.7601x over previous
#include <cuda_runtime.h>
#include <math.h>
#include <stdint.h>

// ---------------------------------------------------------------------------
// QLSTM: T=256, B=256, D=512, H=512.
//  h1 = relu(x@w1+b1); h2 = relu(h1@w2+b2)                (parallel GEMMs)
//  W' = enc_w3 @ gate_w[0:512]  (fp32)   b' = b3@Wx + gb
//  per t: gates = h2[t]@W' + hx@Wh + b'   (fused, weight-stationary persistent)
//         f,i,g,o = act(gates)*mask; cx = f*cx + i*g; hx = o*tanh(cx)
// ---------------------------------------------------------------------------

#define TT      256
#define BBATCH  256
#define HHID    512
#define MROWS   65536            // TT*BBATCH
#define NGATE   2048
#define STATE_SZ (BBATCH*HHID)
#define STACKED_SZ ((size_t)TT*BBATCH*HHID)

// Scratch (device globals; no runtime allocation)
__device__ float d_h1[(size_t)MROWS * 128];
__device__ float d_h2[(size_t)MROWS * 64];
__device__ float d_wp[(size_t)64 * NGATE];
__device__ float d_bp[NGATE];
__device__ float d_hxbuf[2][STATE_SZ];
__device__ float d_mask[4];
// per-m-group barrier state
__device__ unsigned g_cnt[4];
__device__ volatile unsigned g_flag[4];

__device__ __forceinline__ float ftf32(float x) {
    float r; asm("cvt.rna.tf32.f32 %0, %1;" : "=f"(r) : "f"(x)); return r;
}

__device__ __forceinline__ void mma8(float c[4],
                                     uint32_t a0, uint32_t a1, uint32_t a2, uint32_t a3,
                                     uint32_t b0, uint32_t b1) {
    asm volatile(
        "mma.sync.aligned.m16n8k8.row.col.f32.tf32.tf32.f32 "
        "{%0,%1,%2,%3},{%4,%5,%6,%7},{%8,%9},{%0,%1,%2,%3};\n"
        : "+f"(c[0]), "+f"(c[1]), "+f"(c[2]), "+f"(c[3])
        : "r"(a0), "r"(a1), "r"(a2), "r"(a3), "r"(b0), "r"(b1));
}

// ---------------------------------------------------------------------------
// Generic tf32 GEMM (encoder layers): C = act(A@B + bias).
// 64x64 block tile, 4 warps, KC=32, double-buffered smem.
// ---------------------------------------------------------------------------
template<int RELU>
__global__ void __launch_bounds__(128) gemm_tf32_kernel(
    const float* __restrict__ A, const float* __restrict__ B,
    const float* __restrict__ bias, float* __restrict__ C,
    int M, int N, int K, int ldb)
{
    __shared__ float As[2][2304];   // [64][36]
    __shared__ float Bs[2][2304];   // [32][72]

    const int tid = threadIdx.x;
    const int lane = tid & 31, warp = tid >> 5;
    const int m0 = blockIdx.y * 64, n0 = blockIdx.x * 64;
    const int wm = (warp >> 1) * 32, wn = (warp & 1) * 32;
    const int g = lane >> 2, tg = lane & 3;

    float acc[2][4][4];
#pragma unroll
    for (int i = 0; i < 2; i++)
#pragma unroll
        for (int j = 0; j < 4; j++)
#pragma unroll
            for (int e = 0; e < 4; e++) acc[i][j][e] = 0.f;

    const int NC = K >> 5;
    float4 ra[4], rb[4];

    auto loadg = [&](int kc) {
#pragma unroll
        for (int p = 0; p < 4; p++) {
            int idx = p * 512 + tid * 4;
            int am = idx >> 5, ak = idx & 31;
            ra[p] = *(const float4*)(A + (size_t)(m0 + am) * K + kc + ak);
            int bk = idx >> 6, bn = idx & 63;
            rb[p] = *(const float4*)(B + (size_t)(kc + bk) * ldb + n0 + bn);
        }
    };
    auto store = [&](int buf) {
#pragma unroll
        for (int p = 0; p < 4; p++) {
            int idx = p * 512 + tid * 4;
            int am = idx >> 5, ak = idx & 31;
            float4 v = ra[p];
            v.x = ftf32(v.x); v.y = ftf32(v.y); v.z = ftf32(v.z); v.w = ftf32(v.w);
            *(float4*)&As[buf][am * 36 + ak] = v;
            int bk = idx >> 6, bn = idx & 63;
            float4 w = rb[p];
            w.x = ftf32(w.x); w.y = ftf32(w.y); w.z = ftf32(w.z); w.w = ftf32(w.w);
            *(float4*)&Bs[buf][bk * 72 + bn] = w;
        }
    };
    auto compute = [&](int buf) {
#pragma unroll
        for (int kk = 0; kk < 32; kk += 8) {
            uint32_t a[2][4];
#pragma unroll
            for (int mf = 0; mf < 2; mf++) {
                int rbase = wm + mf * 16 + g;
                a[mf][0] = __float_as_uint(As[buf][rbase * 36 + kk + tg]);
                a[mf][1] = __float_as_uint(As[buf][(rbase + 8) * 36 + kk + tg]);
                a[mf][2] = __float_as_uint(As[buf][rbase * 36 + kk + tg + 4]);
                a[mf][3] = __float_as_uint(As[buf][(rbase + 8) * 36 + kk + tg + 4]);
            }
#pragma unroll
            for (int nf = 0; nf < 4; nf++) {
                uint32_t b0 = __float_as_uint(Bs[buf][(kk + tg) * 72 + wn + nf * 8 + g]);
                uint32_t b1 = __float_as_uint(Bs[buf][(kk + tg + 4) * 72 + wn + nf * 8 + g]);
                mma8(acc[0][nf], a[0][0], a[0][1], a[0][2], a[0][3], b0, b1);
                mma8(acc[1][nf], a[1][0], a[1][1], a[1][2], a[1][3], b0, b1);
            }
        }
    };

    loadg(0);
    store(0);
    __syncthreads();
    for (int c = 0; c < NC; c++) {
        int cur = c & 1;
        if (c + 1 < NC) loadg((c + 1) * 32);
        compute(cur);
        if (c + 1 < NC) store(cur ^ 1);
        __syncthreads();
    }

#pragma unroll
    for (int mf = 0; mf < 2; mf++) {
        int r = m0 + wm + mf * 16 + g;
#pragma unroll
        for (int nf = 0; nf < 4; nf++) {
            int col = n0 + wn + nf * 8 + 2 * tg;
            float b0 = bias[col], b1 = bias[col + 1];
            float v0 = acc[mf][nf][0] + b0;
            float v1 = acc[mf][nf][1] + b1;
            float v2 = acc[mf][nf][2] + b0;
            float v3 = acc[mf][nf][3] + b1;
            if (RELU) {
                v0 = fmaxf(v0, 0.f); v1 = fmaxf(v1, 0.f);
                v2 = fmaxf(v2, 0.f); v3 = fmaxf(v3, 0.f);
            }
            float2 p0; p0.x = v0; p0.y = v1;
            float2 p1; p1.x = v2; p1.y = v3;
            *(float2*)(C + (size_t)r * N + col) = p0;
            *(float2*)(C + (size_t)(r + 8) * N + col) = p1;
        }
    }
}

// ---------------------------------------------------------------------------
// W' = enc_w3[64,512] @ gate_w[0:512, 2048]  (full fp32 FFMA)
// ---------------------------------------------------------------------------
__global__ void __launch_bounds__(256) wprime_kernel(
    const float* __restrict__ W3, const float* __restrict__ GW, float* __restrict__ WP)
{
    __shared__ float Asw[64][33];
    __shared__ float Bsw[32][65];
    int tid = threadIdx.x;
    int n0 = blockIdx.x * 64;
    int col = tid & 63;
    int rg = (tid >> 6) * 16;
    float acc[16];
#pragma unroll
    for (int i = 0; i < 16; i++) acc[i] = 0.f;

    for (int kc = 0; kc < 512; kc += 32) {
#pragma unroll
        for (int p = 0; p < 8; p++) {
            int idx = p * 256 + tid;
            int r = idx >> 5, k = idx & 31;
            Asw[r][k] = W3[(size_t)r * 512 + kc + k];
            int bk = idx >> 6, bc = idx & 63;
            Bsw[bk][bc] = GW[(size_t)(kc + bk) * NGATE + n0 + bc];
        }
        __syncthreads();
#pragma unroll 8
        for (int k = 0; k < 32; k++) {
            float bv = Bsw[k][col];
#pragma unroll
            for (int i = 0; i < 16; i++) acc[i] += Asw[rg + i][k] * bv;
        }
        __syncthreads();
    }
#pragma unroll
    for (int i = 0; i < 16; i++)
        WP[(size_t)(rg + i) * NGATE + n0 + col] = acc[i];
}

// b' = eb3 @ gate_w[0:512] + gate_b
__global__ void bprime_kernel(const float* __restrict__ eb3, const float* __restrict__ GW,
                              const float* __restrict__ gb, float* __restrict__ BP)
{
    int n = blockIdx.x * blockDim.x + threadIdx.x;
    if (n < NGATE) {
        float s = gb[n];
        for (int k = 0; k < 512; k++) s += eb3[k] * GW[(size_t)k * NGATE + n];
        BP[n] = s;
    }
}

__global__ void mask_kernel(const float* __restrict__ w1, const float* __restrict__ b1,
                            const float* __restrict__ w2, const float* __restrict__ b2)
{
    if (threadIdx.x == 0 && blockIdx.x == 0) {
        float h[8];
        for (int j = 0; j < 8; j++) {
            float s = b1[j];
            for (int i = 0; i < 4; i++) s += w1[i * 8 + j];
            h[j] = tanhf(s);
        }
        float o[4], mx = -1e30f;
        for (int k = 0; k < 4; k++) {
            float s = b2[k];
            for (int j = 0; j < 8; j++) s += h[j] * w2[j * 4 + k];
            o[k] = s;
            mx = fmaxf(mx, s);
        }
        float e[4], se = 0.f;
        for (int k = 0; k < 4; k++) { e[k] = expf(o[k] - mx); se += e[k]; }
        for (int k = 0; k < 4; k++) d_mask[k] = e[k] / se;
    }
}

__global__ void init_kernel()
{
    int i = blockIdx.x * blockDim.x + threadIdx.x;
    if (i < STATE_SZ) d_hxbuf[0][i] = 0.f;
}

// ---------------------------------------------------------------------------
// Persistent recurrence kernel. Grid = 128 CTAs (4 m-tiles x 32 n-groups),
// 256 threads = 8 warps. Each CTA keeps its Wh slice [512][64] and W' slice
// [64][64] in smem (tf32) for all 256 steps. Per step: 64x576x64 mma tile,
// activation, register-resident cx update, hx chunk write, m-group barrier.
// Smem (floats): Bs 512*72 | Wps 64*72 | As 2*64*68 | gsm 4*64*17 | bsm 64
// ---------------------------------------------------------------------------
#define PS_SMEM_FLOATS 54592   // *4 = 218368 bytes

__global__ void __launch_bounds__(256) lstm_persistent(
    const float* __restrict__ gate_w, const float* __restrict__ wp,
    const float* __restrict__ bp, float* __restrict__ out)
{
    extern __shared__ float sm[];
    float* Bs  = sm;             // 36864
    float* Wps = sm + 36864;     // 4608
    float* As  = sm + 41472;     // 8704 (2 x 64x68)
    float* gsm = sm + 50176;     // 4352 (4 x 64x17)
    float* bsm = sm + 54528;     // 64

    const int tid  = threadIdx.x;
    const int lane = tid & 31, warp = tid >> 5;
    const int g = lane >> 2, tg = lane & 3;
    const int gate = warp & 3;
    const int wm = (warp >> 2) * 32;

    const int ng = blockIdx.x & 31;     // n-group: 16 h cols
    const int mt = blockIdx.x >> 5;     // m-tile
    const int m0 = mt * 64;
    const int h0 = ng * 16;

    const float* Wh = gate_w + (size_t)512 * NGATE;

    // ---- preload weight slices into smem (tf32) ----
    for (int it = tid; it < 8192; it += 256) {        // Wh: 512 k x 16 float4
        int k = it >> 4, c4 = it & 15;
        int gt = c4 >> 2, j4 = c4 & 3;
        float4 v = *(const float4*)(Wh + (size_t)k * NGATE + gt * 512 + h0 + j4 * 4);
        v.x = ftf32(v.x); v.y = ftf32(v.y); v.z = ftf32(v.z); v.w = ftf32(v.w);
        *(float4*)&Bs[k * 72 + gt * 16 + j4 * 4] = v;
    }
    for (int it = tid; it < 1024; it += 256) {        // W': 64 k x 16 float4
        int k = it >> 4, c4 = it & 15;
        int gt = c4 >> 2, j4 = c4 & 3;
        float4 v = *(const float4*)(wp + (size_t)k * NGATE + gt * 512 + h0 + j4 * 4);
        v.x = ftf32(v.x); v.y = ftf32(v.y); v.z = ftf32(v.z); v.w = ftf32(v.w);
        *(float4*)&Wps[k * 72 + gt * 16 + j4 * 4] = v;
    }
    if (tid < 64) {
        int gt = tid >> 4, j = tid & 15;
        bsm[tid] = bp[gt * 512 + h0 + j];
    }
    __syncthreads();

    const float mk = d_mask[gate];

    float cx[4] = {0.f, 0.f, 0.f, 0.f};
    const int um = tid >> 2, uj = (tid & 3) * 4;

    float4 ra[4];
    float acc[2][2][4];

    for (int t = 0; t < TT; t++) {
        const float* hx_in  = d_hxbuf[t & 1];
        float*       hx_out = d_hxbuf[(t + 1) & 1];
        const float* h2t = d_h2 + ((size_t)t * BBATCH + m0) * 64;

#pragma unroll
        for (int i = 0; i < 2; i++)
#pragma unroll
            for (int j = 0; j < 2; j++)
#pragma unroll
                for (int e = 0; e < 4; e++) acc[i][j][e] = 0.f;

        // ---- K loop: chunk 0 = h2 (K=64, B=Wps), chunks 1..8 = hx (B=Bs) ----
        auto loadg = [&](int c) {
#pragma unroll
            for (int p = 0; p < 4; p++) {
                int idx = p * 1024 + tid * 4;
                int am = idx >> 6, ak = idx & 63;
                if (c == 0)
                    ra[p] = *(const float4*)(h2t + (size_t)am * 64 + ak);
                else
                    ra[p] = __ldcg((const float4*)(hx_in + (size_t)(m0 + am) * HHID
                                                   + (c - 1) * 64 + ak));
            }
        };
        auto store = [&](int buf) {
            float* Ab = As + buf * 4352;
#pragma unroll
            for (int p = 0; p < 4; p++) {
                int idx = p * 1024 + tid * 4;
                int am = idx >> 6, ak = idx & 63;
                float4 v = ra[p];
                v.x = ftf32(v.x); v.y = ftf32(v.y); v.z = ftf32(v.z); v.w = ftf32(v.w);
                *(float4*)&Ab[am * 68 + ak] = v;
            }
        };
        auto compute = [&](int buf, const float* Bp) {
            const float* Ab = As + buf * 4352;
#pragma unroll
            for (int kk = 0; kk < 64; kk += 8) {
                int rb0 = wm + g;
                uint32_t a00 = __float_as_uint(Ab[rb0 * 68 + kk + tg]);
                uint32_t a01 = __float_as_uint(Ab[(rb0 + 8) * 68 + kk + tg]);
                uint32_t a02 = __float_as_uint(Ab[rb0 * 68 + kk + tg + 4]);
                uint32_t a03 = __float_as_uint(Ab[(rb0 + 8) * 68 + kk + tg + 4]);
                uint32_t a10 = __float_as_uint(Ab[(rb0 + 16) * 68 + kk + tg]);
                uint32_t a11 = __float_as_uint(Ab[(rb0 + 24) * 68 + kk + tg]);
                uint32_t a12 = __float_as_uint(Ab[(rb0 + 16) * 68 + kk + tg + 4]);
                uint32_t a13 = __float_as_uint(Ab[(rb0 + 24) * 68 + kk + tg + 4]);
#pragma unroll
                for (int nf = 0; nf < 2; nf++) {
                    uint32_t b0 = __float_as_uint(Bp[(kk + tg) * 72 + gate * 16 + nf * 8 + g]);
                    uint32_t b1 = __float_as_uint(Bp[(kk + tg + 4) * 72 + gate * 16 + nf * 8 + g]);
                    mma8(acc[0][nf], a00, a01, a02, a03, b0, b1);
                    mma8(acc[1][nf], a10, a11, a12, a13, b0, b1);
                }
            }
        };

        loadg(0);
        store(0);
        __syncthreads();
#pragma unroll 1
        for (int c = 0; c < 9; c++) {
            int buf = c & 1;
            if (c < 8) loadg(c + 1);
            compute(buf, (c == 0) ? Wps : (Bs + (c - 1) * 4608));
            if (c < 8) store(buf ^ 1);
            __syncthreads();
        }

        // ---- epilogue: bias + activation*mask -> smem exchange ----
#pragma unroll
        for (int mf = 0; mf < 2; mf++) {
            int r0 = wm + mf * 16 + g;
#pragma unroll
            for (int nf = 0; nf < 2; nf++) {
                int j0 = nf * 8 + 2 * tg;
                float b0 = bsm[gate * 16 + j0], b1 = bsm[gate * 16 + j0 + 1];
                float p0 = acc[mf][nf][0] + b0;
                float p1 = acc[mf][nf][1] + b1;
                float p2 = acc[mf][nf][2] + b0;
                float p3 = acc[mf][nf][3] + b1;
                float a0, a1, a2, a3;
                if (gate == 2) {
                    a0 = tanhf(p0); a1 = tanhf(p1); a2 = tanhf(p2); a3 = tanhf(p3);
                } else {
                    a0 = 1.f / (1.f + __expf(-p0));
                    a1 = 1.f / (1.f + __expf(-p1));
                    a2 = 1.f / (1.f + __expf(-p2));
                    a3 = 1.f / (1.f + __expf(-p3));
                }
                float* gp = gsm + gate * 1088;
                gp[r0 * 17 + j0]       = a0 * mk;
                gp[r0 * 17 + j0 + 1]   = a1 * mk;
                gp[(r0 + 8) * 17 + j0]     = a2 * mk;
                gp[(r0 + 8) * 17 + j0 + 1] = a3 * mk;
            }
        }
        __syncthreads();

        // ---- cell update: 4 h-elems per thread, cx in registers ----
        float4 h4, c4v;
        float* hp = &h4.x; float* cp = &c4v.x;
#pragma unroll
        for (int q = 0; q < 4; q++) {
            int jj = uj + q;
            float fv = gsm[0 * 1088 + um * 17 + jj];
            float iv = gsm[1 * 1088 + um * 17 + jj];
            float gv = gsm[2 * 1088 + um * 17 + jj];
            float ov = gsm[3 * 1088 + um * 17 + jj];
            cx[q] = fv * cx[q] + iv * gv;
            cp[q] = cx[q];
            hp[q] = ov * tanhf(cx[q]);
        }
        int gi = (m0 + um) * HHID + h0 + uj;
        *(float4*)(hx_out + gi) = h4;
        *(float4*)(out + ((size_t)t * BBATCH + m0 + um) * HHID + h0 + uj) = h4;
        if (t == TT - 1) {
            *(float4*)(out + STACKED_SZ + gi) = h4;
            *(float4*)(out + STACKED_SZ + STATE_SZ + gi) = c4v;
        }

        // ---- m-group barrier (32 CTAs; all co-resident) ----
        if (t < TT - 1) {
            __threadfence();
            __syncthreads();
            if (tid == 0) {
                unsigned old = atomicAdd(&g_cnt[mt], 1u);
                if (old == 31u) {
                    atomicExch(&g_cnt[mt], 0u);
                    __threadfence();
                    g_flag[mt] = (unsigned)(t + 1);
                } else {
                    while (g_flag[mt] != (unsigned)(t + 1)) { }
                }
                __threadfence();
            }
            __syncthreads();
        }
    }
}

// ---------------------------------------------------------------------------
extern "C" void kernel_launch(void* const* d_in, const int* in_sizes, int n_in,
                              void* d_out, int out_size)
{
    (void)in_sizes; (void)n_in; (void)out_size;
    const float* inputs = (const float*)d_in[0];
    const float* ew1 = (const float*)d_in[1];
    const float* eb1 = (const float*)d_in[2];
    const float* ew2 = (const float*)d_in[3];
    const float* eb2 = (const float*)d_in[4];
    const float* ew3 = (const float*)d_in[5];
    const float* eb3 = (const float*)d_in[6];
    const float* gw  = (const float*)d_in[7];
    const float* gb  = (const float*)d_in[8];
    const float* sw1 = (const float*)d_in[9];
    const float* sb1 = (const float*)d_in[10];
    const float* sw2 = (const float*)d_in[11];
    const float* sb2 = (const float*)d_in[12];
    float* out = (float*)d_out;

    void *ph1, *ph2, *pwp, *pbp;
    cudaGetSymbolAddress(&ph1, d_h1);
    cudaGetSymbolAddress(&ph2, d_h2);
    cudaGetSymbolAddress(&pwp, d_wp);
    cudaGetSymbolAddress(&pbp, d_bp);

    cudaFuncSetAttribute((const void*)lstm_persistent,
                         cudaFuncAttributeMaxDynamicSharedMemorySize,
                         PS_SMEM_FLOATS * 4);

    mask_kernel<<<1, 32>>>(sw1, sb1, sw2, sb2);
    init_kernel<<<(STATE_SZ + 255) / 256, 256>>>();
    wprime_kernel<<<32, 256>>>(ew3, gw, (float*)pwp);
    bprime_kernel<<<8, 256>>>(eb3, gw, gb, (float*)pbp);

    dim3 tb(128);
    // h1 = relu(x @ w1 + b1)       [65536,512]x[512,128]
    gemm_tf32_kernel<1><<<dim3(2, MROWS / 64), tb>>>(
        inputs, ew1, eb1, (float*)ph1, MROWS, 128, 512, 128);
    // h2 = relu(h1 @ w2 + b2)      [65536,128]x[128,64]
    gemm_tf32_kernel<1><<<dim3(1, MROWS / 64), tb>>>(
        (const float*)ph1, ew2, eb2, (float*)ph2, MROWS, 64, 128, 64);

    // persistent fused recurrence
    lstm_persistent<<<128, 256, PS_SMEM_FLOATS * 4>>>(
        gw, (const float*)pwp, (const float*)pbp, out);
}

// round 5
// speedup vs baseline: 2.6331x; 1.4960x over previous
#include <cuda_runtime.h>
#include <math.h>
#include <stdint.h>

// ---------------------------------------------------------------------------
// QLSTM: T=256, B=256, D=512, H=512.
//  h1 = relu(x@w1+b1); h2 = tf32(relu(h1@w2+b2))          (parallel GEMMs)
//  W' = enc_w3 @ gate_w[0:512]  (fp32)   b' = b3@Wx + gb
//  per t: gates = h2[t]@W' + hx@Wh + b'   (persistent, weight-stationary)
//         f,i,g,o = act(gates)*mask; cx = f*cx + i*g; hx = o*tanh(cx)
// All GEMMs tf32 mma.sync, fp32 accumulate. hx stored pre-rounded to tf32
// (recurrence buffer only; `out` keeps full-precision hx).
// ---------------------------------------------------------------------------

#define TT      256
#define BBATCH  256
#define HHID    512
#define MROWS   65536
#define NGATE   2048
#define STATE_SZ (BBATCH*HHID)
#define STACKED_SZ ((size_t)TT*BBATCH*HHID)

__device__ float d_h1[(size_t)MROWS * 128];
__device__ float d_h2[(size_t)MROWS * 64];
__device__ float d_wp[(size_t)64 * NGATE];
__device__ float d_bp[NGATE];
__device__ float d_hxbuf[2][STATE_SZ];
__device__ float d_mask[4];
__device__ unsigned g_arrive[4][32];   // monotone per-(mt,ng) step counters

__device__ __forceinline__ float ftf32(float x) {
    float r; asm("cvt.rna.tf32.f32 %0, %1;" : "=f"(r) : "f"(x)); return r;
}

__device__ __forceinline__ void mma8(float c[4],
                                     uint32_t a0, uint32_t a1, uint32_t a2, uint32_t a3,
                                     uint32_t b0, uint32_t b1) {
    asm volatile(
        "mma.sync.aligned.m16n8k8.row.col.f32.tf32.tf32.f32 "
        "{%0,%1,%2,%3},{%4,%5,%6,%7},{%8,%9},{%0,%1,%2,%3};\n"
        : "+f"(c[0]), "+f"(c[1]), "+f"(c[2]), "+f"(c[3])
        : "r"(a0), "r"(a1), "r"(a2), "r"(a3), "r"(b0), "r"(b1));
}

__device__ __forceinline__ void cpa16(uint32_t dst, const void* src) {
    asm volatile("cp.async.cg.shared.global [%0], [%1], 16;\n"
                 :: "r"(dst), "l"(src));
}
#define CP_COMMIT() asm volatile("cp.async.commit_group;\n" ::: "memory")
#define CP_WAIT(n)  asm volatile("cp.async.wait_group %0;\n" :: "n"(n) : "memory")

__device__ __forceinline__ float fsig(float x) {
    return __fdividef(1.f, 1.f + __expf(-x));
}
__device__ __forceinline__ float ftanh(float x) {
    return __fdividef(2.f, 1.f + __expf(-2.f * x)) - 1.f;
}

// ---------------------------------------------------------------------------
// Generic tf32 GEMM (encoder layers): C = maybe_round(act(A@B + bias)).
// ---------------------------------------------------------------------------
template<int RELU, int ROUND>
__global__ void __launch_bounds__(128) gemm_tf32_kernel(
    const float* __restrict__ A, const float* __restrict__ B,
    const float* __restrict__ bias, float* __restrict__ C,
    int M, int N, int K, int ldb)
{
    __shared__ float As[2][2304];   // [64][36]
    __shared__ float Bs[2][2304];   // [32][72]

    const int tid = threadIdx.x;
    const int lane = tid & 31, warp = tid >> 5;
    const int m0 = blockIdx.y * 64, n0 = blockIdx.x * 64;
    const int wm = (warp >> 1) * 32, wn = (warp & 1) * 32;
    const int g = lane >> 2, tg = lane & 3;

    float acc[2][4][4];
#pragma unroll
    for (int i = 0; i < 2; i++)
#pragma unroll
        for (int j = 0; j < 4; j++)
#pragma unroll
            for (int e = 0; e < 4; e++) acc[i][j][e] = 0.f;

    const int NC = K >> 5;
    float4 ra[4], rb[4];

    auto loadg = [&](int kc) {
#pragma unroll
        for (int p = 0; p < 4; p++) {
            int idx = p * 512 + tid * 4;
            int am = idx >> 5, ak = idx & 31;
            ra[p] = *(const float4*)(A + (size_t)(m0 + am) * K + kc + ak);
            int bk = idx >> 6, bn = idx & 63;
            rb[p] = *(const float4*)(B + (size_t)(kc + bk) * ldb + n0 + bn);
        }
    };
    auto store = [&](int buf) {
#pragma unroll
        for (int p = 0; p < 4; p++) {
            int idx = p * 512 + tid * 4;
            int am = idx >> 5, ak = idx & 31;
            float4 v = ra[p];
            v.x = ftf32(v.x); v.y = ftf32(v.y); v.z = ftf32(v.z); v.w = ftf32(v.w);
            *(float4*)&As[buf][am * 36 + ak] = v;
            int bk = idx >> 6, bn = idx & 63;
            float4 w = rb[p];
            w.x = ftf32(w.x); w.y = ftf32(w.y); w.z = ftf32(w.z); w.w = ftf32(w.w);
            *(float4*)&Bs[buf][bk * 72 + bn] = w;
        }
    };
    auto compute = [&](int buf) {
#pragma unroll
        for (int kk = 0; kk < 32; kk += 8) {
            uint32_t a[2][4];
#pragma unroll
            for (int mf = 0; mf < 2; mf++) {
                int rbase = wm + mf * 16 + g;
                a[mf][0] = __float_as_uint(As[buf][rbase * 36 + kk + tg]);
                a[mf][1] = __float_as_uint(As[buf][(rbase + 8) * 36 + kk + tg]);
                a[mf][2] = __float_as_uint(As[buf][rbase * 36 + kk + tg + 4]);
                a[mf][3] = __float_as_uint(As[buf][(rbase + 8) * 36 + kk + tg + 4]);
            }
#pragma unroll
            for (int nf = 0; nf < 4; nf++) {
                uint32_t b0 = __float_as_uint(Bs[buf][(kk + tg) * 72 + wn + nf * 8 + g]);
                uint32_t b1 = __float_as_uint(Bs[buf][(kk + tg + 4) * 72 + wn + nf * 8 + g]);
                mma8(acc[0][nf], a[0][0], a[0][1], a[0][2], a[0][3], b0, b1);
                mma8(acc[1][nf], a[1][0], a[1][1], a[1][2], a[1][3], b0, b1);
            }
        }
    };

    loadg(0);
    store(0);
    __syncthreads();
    for (int c = 0; c < NC; c++) {
        int cur = c & 1;
        if (c + 1 < NC) loadg((c + 1) * 32);
        compute(cur);
        if (c + 1 < NC) store(cur ^ 1);
        __syncthreads();
    }

#pragma unroll
    for (int mf = 0; mf < 2; mf++) {
        int r = m0 + wm + mf * 16 + g;
#pragma unroll
        for (int nf = 0; nf < 4; nf++) {
            int col = n0 + wn + nf * 8 + 2 * tg;
            float b0 = bias[col], b1 = bias[col + 1];
            float v0 = acc[mf][nf][0] + b0;
            float v1 = acc[mf][nf][1] + b1;
            float v2 = acc[mf][nf][2] + b0;
            float v3 = acc[mf][nf][3] + b1;
            if (RELU) {
                v0 = fmaxf(v0, 0.f); v1 = fmaxf(v1, 0.f);
                v2 = fmaxf(v2, 0.f); v3 = fmaxf(v3, 0.f);
            }
            if (ROUND) {
                v0 = ftf32(v0); v1 = ftf32(v1);
                v2 = ftf32(v2); v3 = ftf32(v3);
            }
            float2 p0; p0.x = v0; p0.y = v1;
            float2 p1; p1.x = v2; p1.y = v3;
            *(float2*)(C + (size_t)r * N + col) = p0;
            *(float2*)(C + (size_t)(r + 8) * N + col) = p1;
        }
    }
}

// ---------------------------------------------------------------------------
// W' = enc_w3[64,512] @ gate_w[0:512, 2048]  (full fp32 FFMA)
// ---------------------------------------------------------------------------
__global__ void __launch_bounds__(256) wprime_kernel(
    const float* __restrict__ W3, const float* __restrict__ GW, float* __restrict__ WP)
{
    __shared__ float Asw[64][33];
    __shared__ float Bsw[32][65];
    int tid = threadIdx.x;
    int n0 = blockIdx.x * 64;
    int col = tid & 63;
    int rg = (tid >> 6) * 16;
    float acc[16];
#pragma unroll
    for (int i = 0; i < 16; i++) acc[i] = 0.f;

    for (int kc = 0; kc < 512; kc += 32) {
#pragma unroll
        for (int p = 0; p < 8; p++) {
            int idx = p * 256 + tid;
            int r = idx >> 5, k = idx & 31;
            Asw[r][k] = W3[(size_t)r * 512 + kc + k];
            int bk = idx >> 6, bc = idx & 63;
            Bsw[bk][bc] = GW[(size_t)(kc + bk) * NGATE + n0 + bc];
        }
        __syncthreads();
#pragma unroll 8
        for (int k = 0; k < 32; k++) {
            float bv = Bsw[k][col];
#pragma unroll
            for (int i = 0; i < 16; i++) acc[i] += Asw[rg + i][k] * bv;
        }
        __syncthreads();
    }
#pragma unroll
    for (int i = 0; i < 16; i++)
        WP[(size_t)(rg + i) * NGATE + n0 + col] = acc[i];
}

// b' = eb3 @ gate_w[0:512] + gate_b     (64 blocks x 32 threads, unroll-8 MLP)
__global__ void __launch_bounds__(32) bprime_kernel(
    const float* __restrict__ eb3, const float* __restrict__ GW,
    const float* __restrict__ gb, float* __restrict__ BP)
{
    int n = blockIdx.x * 32 + threadIdx.x;
    float s = gb[n];
#pragma unroll 8
    for (int k = 0; k < 512; k++) s += eb3[k] * GW[(size_t)k * NGATE + n];
    BP[n] = s;
}

__global__ void mask_kernel(const float* __restrict__ w1, const float* __restrict__ b1,
                            const float* __restrict__ w2, const float* __restrict__ b2)
{
    if (threadIdx.x == 0 && blockIdx.x == 0) {
        float h[8];
        for (int j = 0; j < 8; j++) {
            float s = b1[j];
            for (int i = 0; i < 4; i++) s += w1[i * 8 + j];
            h[j] = tanhf(s);
        }
        float o[4], mx = -1e30f;
        for (int k = 0; k < 4; k++) {
            float s = b2[k];
            for (int j = 0; j < 8; j++) s += h[j] * w2[j * 4 + k];
            o[k] = s;
            mx = fmaxf(mx, s);
        }
        float e[4], se = 0.f;
        for (int k = 0; k < 4; k++) { e[k] = expf(o[k] - mx); se += e[k]; }
        for (int k = 0; k < 4; k++) d_mask[k] = e[k] / se;
    }
}

// ---------------------------------------------------------------------------
// Persistent recurrence. Grid = 128 CTAs (4 m-tiles x 32 n-groups), 8 warps.
// Smem (floats): Bs 512*72 | Wps 64*72 | As 3*(64*68) | bsm 64  = 54592.
// Chunk k (k=0: h2xW', k=1..8: hx cols) lives in As buf k%3 via cp.async.cg,
// issued 2 chunks ahead. gsm epilogue exchange aliases As buf2.
// Inter-CTA sync: monotone release/acquire flag slots (replay-safe).
// ---------------------------------------------------------------------------
#define PS_SMEM_FLOATS 54592   // 218368 bytes
#define AS_STRIDE 68
#define AS_BUF    4352         // 64*68

__global__ void __launch_bounds__(256) lstm_persistent(
    const float* __restrict__ gate_w, const float* __restrict__ wp,
    const float* __restrict__ bp, float* __restrict__ out)
{
    extern __shared__ float sm[];
    float* Bs  = sm;                    // 36864
    float* Wps = sm + 36864;            // 4608
    float* As  = sm + 41472;            // 3*4352 = 13056
    float* bsm = sm + 54528;            // 64
    float* gsm = As + 2 * AS_BUF;       // alias buf2 (4*64*17 = 4352)

    const int tid  = threadIdx.x;
    const int lane = tid & 31, warp = tid >> 5;
    const int g = lane >> 2, tg = lane & 3;
    const int gate = warp & 3;
    const int wm = (warp >> 2) * 32;

    const int ng = blockIdx.x & 31;     // 16 h cols
    const int mt = blockIdx.x >> 5;     // m-tile
    const int m0 = mt * 64;
    const int h0 = ng * 16;

    const float* Wh = gate_w + (size_t)512 * NGATE;
    const uint32_t as_u32 = (uint32_t)__cvta_generic_to_shared(As);

    // monotone flag base (uniform across slots at kernel entry)
    unsigned fbase = *((volatile unsigned*)&g_arrive[mt][ng]);

    // ---- preload weight slices (tf32) + bias ----
    for (int it = tid; it < 8192; it += 256) {        // Wh: 512 k x 16 f4
        int k = it >> 4, c4 = it & 15;
        int gt = c4 >> 2, j4 = c4 & 3;
        float4 v = *(const float4*)(Wh + (size_t)k * NGATE + gt * 512 + h0 + j4 * 4);
        v.x = ftf32(v.x); v.y = ftf32(v.y); v.z = ftf32(v.z); v.w = ftf32(v.w);
        *(float4*)&Bs[k * 72 + gt * 16 + j4 * 4] = v;
    }
    for (int it = tid; it < 1024; it += 256) {        // W': 64 k x 16 f4
        int k = it >> 4, c4 = it & 15;
        int gt = c4 >> 2, j4 = c4 & 3;
        float4 v = *(const float4*)(wp + (size_t)k * NGATE + gt * 512 + h0 + j4 * 4);
        v.x = ftf32(v.x); v.y = ftf32(v.y); v.z = ftf32(v.z); v.w = ftf32(v.w);
        *(float4*)&Wps[k * 72 + gt * 16 + j4 * 4] = v;
    }
    if (tid < 64) {
        int gt = tid >> 4, j = tid & 15;
        bsm[tid] = bp[gt * 512 + h0 + j];
    }
    __syncthreads();

    const float mk = d_mask[gate];
    float cx[4] = {0.f, 0.f, 0.f, 0.f};
    const int um = tid >> 2, uj = (tid & 3) * 4;

    // cp.async issue of one 64x64 chunk into As buffer `buf`
    auto issueA = [&](int buf, const float* src, int ld) {
#pragma unroll
        for (int p = 0; p < 4; p++) {
            int idx = p * 256 + tid;
            int row = idx >> 4, c4 = (idx & 15) << 2;
            cpa16(as_u32 + (uint32_t)(buf * AS_BUF + row * AS_STRIDE + c4) * 4u,
                  src + (size_t)row * ld + c4);
        }
        CP_COMMIT();
    };

    float acc[2][2][4];
    auto compute = [&](const float* Ab, const float* Bp) {
#pragma unroll
        for (int kk = 0; kk < 64; kk += 8) {
            int rb0 = wm + g;
            uint32_t a00 = __float_as_uint(Ab[rb0 * AS_STRIDE + kk + tg]);
            uint32_t a01 = __float_as_uint(Ab[(rb0 + 8) * AS_STRIDE + kk + tg]);
            uint32_t a02 = __float_as_uint(Ab[rb0 * AS_STRIDE + kk + tg + 4]);
            uint32_t a03 = __float_as_uint(Ab[(rb0 + 8) * AS_STRIDE + kk + tg + 4]);
            uint32_t a10 = __float_as_uint(Ab[(rb0 + 16) * AS_STRIDE + kk + tg]);
            uint32_t a11 = __float_as_uint(Ab[(rb0 + 24) * AS_STRIDE + kk + tg]);
            uint32_t a12 = __float_as_uint(Ab[(rb0 + 16) * AS_STRIDE + kk + tg + 4]);
            uint32_t a13 = __float_as_uint(Ab[(rb0 + 24) * AS_STRIDE + kk + tg + 4]);
#pragma unroll
            for (int nf = 0; nf < 2; nf++) {
                uint32_t b0 = __float_as_uint(Bp[(kk + tg) * 72 + gate * 16 + nf * 8 + g]);
                uint32_t b1 = __float_as_uint(Bp[(kk + tg + 4) * 72 + gate * 16 + nf * 8 + g]);
                mma8(acc[0][nf], a00, a01, a02, a03, b0, b1);
                mma8(acc[1][nf], a10, a11, a12, a13, b0, b1);
            }
        }
    };

    // prologue: h2[0] -> buf0
    issueA(0, d_h2 + (size_t)m0 * 64, 64);

    for (int t = 0; t < TT; t++) {
        const float* hx_in  = d_hxbuf[t & 1];
        float*       hx_out = d_hxbuf[(t + 1) & 1];

#pragma unroll
        for (int i = 0; i < 2; i++)
#pragma unroll
            for (int j = 0; j < 2; j++)
#pragma unroll
                for (int e = 0; e < 4; e++) acc[i][j][e] = 0.f;

        CP_WAIT(0);
        __syncthreads();
        compute(As, Wps);                  // chunk 0 (h2 x W'), overlaps barrier

        if (t == 0) {
            __syncthreads();               // all warps done reading buf0
            issueA(0, d_h2 + (size_t)(256 + m0) * 64, 64);   // h2[1]
        } else {
            // wait for step-t hx (flags >= fbase + t), 32 parallel slots
            if (tid < 32) {
                unsigned tgt = fbase + (unsigned)t;
                const unsigned* fp = &g_arrive[mt][tid];
                unsigned v;
                while (true) {
                    asm volatile("ld.acquire.gpu.global.u32 %0, [%1];"
                                 : "=r"(v) : "l"(fp));
                    if ((int)(v - tgt) >= 0) break;
                    __nanosleep(32);
                }
            }
            __syncthreads();
            const float* hxm = hx_in + (size_t)m0 * HHID;
            issueA(1, hxm,      HHID);     // chunk 1
            issueA(2, hxm + 64, HHID);     // chunk 2
#pragma unroll
            for (int c = 1; c <= 8; c++) {
                if (c == 8) {
                    if (t == TT - 1) { CP_WAIT(0); } else { CP_WAIT(1); }
                } else {
                    CP_WAIT(1);
                }
                __syncthreads();
                compute(As + (c % 3) * AS_BUF, Bs + (c - 1) * 4608);
                if (c <= 6) {
                    issueA((c + 2) % 3, hxm + (c + 1) * 64, HHID);
                } else if (c == 7 && t + 1 < TT) {
                    issueA(0, d_h2 + ((size_t)(t + 1) * 256 + m0) * 64, 64);
                }
            }
        }

        __syncthreads();    // As buf2 reads done -> gsm alias safe

        // ---- epilogue: bias + activation*mask -> gsm exchange ----
#pragma unroll
        for (int mf = 0; mf < 2; mf++) {
            int r0 = wm + mf * 16 + g;
#pragma unroll
            for (int nf = 0; nf < 2; nf++) {
                int j0 = nf * 8 + 2 * tg;
                float b0 = bsm[gate * 16 + j0], b1 = bsm[gate * 16 + j0 + 1];
                float p0 = acc[mf][nf][0] + b0;
                float p1 = acc[mf][nf][1] + b1;
                float p2 = acc[mf][nf][2] + b0;
                float p3 = acc[mf][nf][3] + b1;
                float a0, a1, a2, a3;
                if (gate == 2) {
                    a0 = ftanh(p0); a1 = ftanh(p1); a2 = ftanh(p2); a3 = ftanh(p3);
                } else {
                    a0 = fsig(p0); a1 = fsig(p1); a2 = fsig(p2); a3 = fsig(p3);
                }
                float* gp = gsm + gate * 1088;
                gp[r0 * 17 + j0]           = a0 * mk;
                gp[r0 * 17 + j0 + 1]       = a1 * mk;
                gp[(r0 + 8) * 17 + j0]     = a2 * mk;
                gp[(r0 + 8) * 17 + j0 + 1] = a3 * mk;
            }
        }
        __syncthreads();

        // ---- cell update (cx in registers) ----
        float4 h4, c4v, h4r;
        float* hp = &h4.x; float* cp = &c4v.x; float* hr = &h4r.x;
#pragma unroll
        for (int q = 0; q < 4; q++) {
            int jj = uj + q;
            float fv = gsm[0 * 1088 + um * 17 + jj];
            float iv = gsm[1 * 1088 + um * 17 + jj];
            float gv = gsm[2 * 1088 + um * 17 + jj];
            float ov = gsm[3 * 1088 + um * 17 + jj];
            cx[q] = fv * cx[q] + iv * gv;
            cp[q] = cx[q];
            float hn = ov * ftanh(cx[q]);
            hp[q] = hn;
            hr[q] = ftf32(hn);
        }
        int gi = (m0 + um) * HHID + h0 + uj;
        *(float4*)(hx_out + gi) = h4r;                                   // tf32 for recurrence
        *(float4*)(out + ((size_t)t * BBATCH + m0 + um) * HHID + h0 + uj) = h4;
        if (t == TT - 1) {
            *(float4*)(out + STACKED_SZ + gi) = h4;
            *(float4*)(out + STACKED_SZ + STATE_SZ + gi) = c4v;
        }

        __syncthreads();
        if (t < TT - 1 && tid == 0) {
            unsigned nv = fbase + (unsigned)(t + 1);
            asm volatile("st.release.gpu.global.u32 [%0], %1;"
                         :: "l"(&g_arrive[mt][ng]), "r"(nv) : "memory");
        }
    }
}

// ---------------------------------------------------------------------------
extern "C" void kernel_launch(void* const* d_in, const int* in_sizes, int n_in,
                              void* d_out, int out_size)
{
    (void)in_sizes; (void)n_in; (void)out_size;
    const float* inputs = (const float*)d_in[0];
    const float* ew1 = (const float*)d_in[1];
    const float* eb1 = (const float*)d_in[2];
    const float* ew2 = (const float*)d_in[3];
    const float* eb2 = (const float*)d_in[4];
    const float* ew3 = (const float*)d_in[5];
    const float* eb3 = (const float*)d_in[6];
    const float* gw  = (const float*)d_in[7];
    const float* gb  = (const float*)d_in[8];
    const float* sw1 = (const float*)d_in[9];
    const float* sb1 = (const float*)d_in[10];
    const float* sw2 = (const float*)d_in[11];
    const float* sb2 = (const float*)d_in[12];
    float* out = (float*)d_out;

    void *ph1, *ph2, *pwp, *pbp;
    cudaGetSymbolAddress(&ph1, d_h1);
    cudaGetSymbolAddress(&ph2, d_h2);
    cudaGetSymbolAddress(&pwp, d_wp);
    cudaGetSymbolAddress(&pbp, d_bp);

    cudaFuncSetAttribute((const void*)lstm_persistent,
                         cudaFuncAttributeMaxDynamicSharedMemorySize,
                         PS_SMEM_FLOATS * 4);

    mask_kernel<<<1, 32>>>(sw1, sb1, sw2, sb2);
    wprime_kernel<<<32, 256>>>(ew3, gw, (float*)pwp);
    bprime_kernel<<<64, 32>>>(eb3, gw, gb, (float*)pbp);

    dim3 tb(128);
    // h1 = relu(x @ w1 + b1)              [65536,512]x[512,128]
    gemm_tf32_kernel<1, 0><<<dim3(2, MROWS / 64), tb>>>(
        inputs, ew1, eb1, (float*)ph1, MROWS, 128, 512, 128);
    // h2 = tf32(relu(h1 @ w2 + b2))       [65536,128]x[128,64]
    gemm_tf32_kernel<1, 1><<<dim3(1, MROWS / 64), tb>>>(
        (const float*)ph1, ew2, eb2, (float*)ph2, MROWS, 64, 128, 64);

    // persistent fused recurrence
    lstm_persistent<<<128, 256, PS_SMEM_FLOATS * 4>>>(
        gw, (const float*)pwp, (const float*)pbp, out);
}

// round 6
// speedup vs baseline: 2.7032x; 1.0266x over previous
#include <cuda_runtime.h>
#include <math.h>
#include <stdint.h>

// ---------------------------------------------------------------------------
// QLSTM: T=256, B=256, D=512, H=512.
//  h1 = relu(x@w1+b1); h2 = tf32(relu(h1@w2+b2))          (parallel GEMMs)
//  W' = enc_w3 @ gate_w[0:512]  (fp32)   b' = b3@Wx + gb
//  per t: gates = h2[t]@W' + hx@Wh + b'   (persistent, weight-stationary)
//         f,i,g,o = act(gates)*mask; cx = f*cx + i*g; hx = o*tanh(cx)
// All GEMMs tf32 mma.sync, fp32 accumulate. hx stored pre-rounded to tf32
// (recurrence buffer only; `out` keeps full-precision hx).
// ---------------------------------------------------------------------------

#define TT      256
#define BBATCH  256
#define HHID    512
#define MROWS   65536
#define NGATE   2048
#define STATE_SZ (BBATCH*HHID)
#define STACKED_SZ ((size_t)TT*BBATCH*HHID)

__device__ float d_h1[(size_t)MROWS * 128];
__device__ float d_h2[(size_t)MROWS * 64];
__device__ float d_wp[(size_t)64 * NGATE];
__device__ float d_bp[NGATE];
__device__ float d_hxbuf[2][STATE_SZ];
__device__ float d_mask[4];
__device__ unsigned g_arrive[4][32];   // monotone per-(mt,ng) step counters

__device__ __forceinline__ float ftf32(float x) {
    float r; asm("cvt.rna.tf32.f32 %0, %1;" : "=f"(r) : "f"(x)); return r;
}

__device__ __forceinline__ void mma8(float c[4],
                                     uint32_t a0, uint32_t a1, uint32_t a2, uint32_t a3,
                                     uint32_t b0, uint32_t b1) {
    asm volatile(
        "mma.sync.aligned.m16n8k8.row.col.f32.tf32.tf32.f32 "
        "{%0,%1,%2,%3},{%4,%5,%6,%7},{%8,%9},{%0,%1,%2,%3};\n"
        : "+f"(c[0]), "+f"(c[1]), "+f"(c[2]), "+f"(c[3])
        : "r"(a0), "r"(a1), "r"(a2), "r"(a3), "r"(b0), "r"(b1));
}

__device__ __forceinline__ void cpa16(uint32_t dst, const void* src) {
    asm volatile("cp.async.cg.shared.global [%0], [%1], 16;\n"
                 :: "r"(dst), "l"(src));
}
#define CP_COMMIT() asm volatile("cp.async.commit_group;\n" ::: "memory")
#define CP_WAIT(n)  asm volatile("cp.async.wait_group %0;\n" :: "n"(n) : "memory")

__device__ __forceinline__ float fsig(float x) {
    return __fdividef(1.f, 1.f + __expf(-x));
}
__device__ __forceinline__ float ftanh(float x) {
    return __fdividef(2.f, 1.f + __expf(-2.f * x)) - 1.f;
}

// ---------------------------------------------------------------------------
// Generic tf32 GEMM (encoder layers): C = maybe_round(act(A@B + bias)).
// ---------------------------------------------------------------------------
template<int RELU, int ROUND>
__global__ void __launch_bounds__(128) gemm_tf32_kernel(
    const float* __restrict__ A, const float* __restrict__ B,
    const float* __restrict__ bias, float* __restrict__ C,
    int M, int N, int K, int ldb)
{
    __shared__ float As[2][2304];   // [64][36]
    __shared__ float Bs[2][2304];   // [32][72]

    const int tid = threadIdx.x;
    const int lane = tid & 31, warp = tid >> 5;
    const int m0 = blockIdx.y * 64, n0 = blockIdx.x * 64;
    const int wm = (warp >> 1) * 32, wn = (warp & 1) * 32;
    const int g = lane >> 2, tg = lane & 3;

    float acc[2][4][4];
#pragma unroll
    for (int i = 0; i < 2; i++)
#pragma unroll
        for (int j = 0; j < 4; j++)
#pragma unroll
            for (int e = 0; e < 4; e++) acc[i][j][e] = 0.f;

    const int NC = K >> 5;
    float4 ra[4], rb[4];

    auto loadg = [&](int kc) {
#pragma unroll
        for (int p = 0; p < 4; p++) {
            int idx = p * 512 + tid * 4;
            int am = idx >> 5, ak = idx & 31;
            ra[p] = *(const float4*)(A + (size_t)(m0 + am) * K + kc + ak);
            int bk = idx >> 6, bn = idx & 63;
            rb[p] = *(const float4*)(B + (size_t)(kc + bk) * ldb + n0 + bn);
        }
    };
    auto store = [&](int buf) {
#pragma unroll
        for (int p = 0; p < 4; p++) {
            int idx = p * 512 + tid * 4;
            int am = idx >> 5, ak = idx & 31;
            float4 v = ra[p];
            v.x = ftf32(v.x); v.y = ftf32(v.y); v.z = ftf32(v.z); v.w = ftf32(v.w);
            *(float4*)&As[buf][am * 36 + ak] = v;
            int bk = idx >> 6, bn = idx & 63;
            float4 w = rb[p];
            w.x = ftf32(w.x); w.y = ftf32(w.y); w.z = ftf32(w.z); w.w = ftf32(w.w);
            *(float4*)&Bs[buf][bk * 72 + bn] = w;
        }
    };
    auto compute = [&](int buf) {
#pragma unroll
        for (int kk = 0; kk < 32; kk += 8) {
            uint32_t a[2][4];
#pragma unroll
            for (int mf = 0; mf < 2; mf++) {
                int rbase = wm + mf * 16 + g;
                a[mf][0] = __float_as_uint(As[buf][rbase * 36 + kk + tg]);
                a[mf][1] = __float_as_uint(As[buf][(rbase + 8) * 36 + kk + tg]);
                a[mf][2] = __float_as_uint(As[buf][rbase * 36 + kk + tg + 4]);
                a[mf][3] = __float_as_uint(As[buf][(rbase + 8) * 36 + kk + tg + 4]);
            }
#pragma unroll
            for (int nf = 0; nf < 4; nf++) {
                uint32_t b0 = __float_as_uint(Bs[buf][(kk + tg) * 72 + wn + nf * 8 + g]);
                uint32_t b1 = __float_as_uint(Bs[buf][(kk + tg + 4) * 72 + wn + nf * 8 + g]);
                mma8(acc[0][nf], a[0][0], a[0][1], a[0][2], a[0][3], b0, b1);
                mma8(acc[1][nf], a[1][0], a[1][1], a[1][2], a[1][3], b0, b1);
            }
        }
    };

    loadg(0);
    store(0);
    __syncthreads();
    for (int c = 0; c < NC; c++) {
        int cur = c & 1;
        if (c + 1 < NC) loadg((c + 1) * 32);
        compute(cur);
        if (c + 1 < NC) store(cur ^ 1);
        __syncthreads();
    }

#pragma unroll
    for (int mf = 0; mf < 2; mf++) {
        int r = m0 + wm + mf * 16 + g;
#pragma unroll
        for (int nf = 0; nf < 4; nf++) {
            int col = n0 + wn + nf * 8 + 2 * tg;
            float b0 = bias[col], b1 = bias[col + 1];
            float v0 = acc[mf][nf][0] + b0;
            float v1 = acc[mf][nf][1] + b1;
            float v2 = acc[mf][nf][2] + b0;
            float v3 = acc[mf][nf][3] + b1;
            if (RELU) {
                v0 = fmaxf(v0, 0.f); v1 = fmaxf(v1, 0.f);
                v2 = fmaxf(v2, 0.f); v3 = fmaxf(v3, 0.f);
            }
            if (ROUND) {
                v0 = ftf32(v0); v1 = ftf32(v1);
                v2 = ftf32(v2); v3 = ftf32(v3);
            }
            float2 p0; p0.x = v0; p0.y = v1;
            float2 p1; p1.x = v2; p1.y = v3;
            *(float2*)(C + (size_t)r * N + col) = p0;
            *(float2*)(C + (size_t)(r + 8) * N + col) = p1;
        }
    }
}

// ---------------------------------------------------------------------------
// W' = enc_w3[64,512] @ gate_w[0:512, 2048]  (full fp32 FFMA)
// ---------------------------------------------------------------------------
__global__ void __launch_bounds__(256) wprime_kernel(
    const float* __restrict__ W3, const float* __restrict__ GW, float* __restrict__ WP)
{
    __shared__ float Asw[64][33];
    __shared__ float Bsw[32][65];
    int tid = threadIdx.x;
    int n0 = blockIdx.x * 64;
    int col = tid & 63;
    int rg = (tid >> 6) * 16;
    float acc[16];
#pragma unroll
    for (int i = 0; i < 16; i++) acc[i] = 0.f;

    for (int kc = 0; kc < 512; kc += 32) {
#pragma unroll
        for (int p = 0; p < 8; p++) {
            int idx = p * 256 + tid;
            int r = idx >> 5, k = idx & 31;
            Asw[r][k] = W3[(size_t)r * 512 + kc + k];
            int bk = idx >> 6, bc = idx & 63;
            Bsw[bk][bc] = GW[(size_t)(kc + bk) * NGATE + n0 + bc];
        }
        __syncthreads();
#pragma unroll 8
        for (int k = 0; k < 32; k++) {
            float bv = Bsw[k][col];
#pragma unroll
            for (int i = 0; i < 16; i++) acc[i] += Asw[rg + i][k] * bv;
        }
        __syncthreads();
    }
#pragma unroll
    for (int i = 0; i < 16; i++)
        WP[(size_t)(rg + i) * NGATE + n0 + col] = acc[i];
}

// b' = eb3 @ gate_w[0:512] + gate_b     (64 blocks x 32 threads, unroll-8 MLP)
__global__ void __launch_bounds__(32) bprime_kernel(
    const float* __restrict__ eb3, const float* __restrict__ GW,
    const float* __restrict__ gb, float* __restrict__ BP)
{
    int n = blockIdx.x * 32 + threadIdx.x;
    float s = gb[n];
#pragma unroll 8
    for (int k = 0; k < 512; k++) s += eb3[k] * GW[(size_t)k * NGATE + n];
    BP[n] = s;
}

__global__ void mask_kernel(const float* __restrict__ w1, const float* __restrict__ b1,
                            const float* __restrict__ w2, const float* __restrict__ b2)
{
    if (threadIdx.x == 0 && blockIdx.x == 0) {
        float h[8];
        for (int j = 0; j < 8; j++) {
            float s = b1[j];
            for (int i = 0; i < 4; i++) s += w1[i * 8 + j];
            h[j] = tanhf(s);
        }
        float o[4], mx = -1e30f;
        for (int k = 0; k < 4; k++) {
            float s = b2[k];
            for (int j = 0; j < 8; j++) s += h[j] * w2[j * 4 + k];
            o[k] = s;
            mx = fmaxf(mx, s);
        }
        float e[4], se = 0.f;
        for (int k = 0; k < 4; k++) { e[k] = expf(o[k] - mx); se += e[k]; }
        for (int k = 0; k < 4; k++) d_mask[k] = e[k] / se;
    }
}

// ---------------------------------------------------------------------------
// Persistent recurrence. Grid = 128 CTAs (4 m-tiles x 32 n-groups), 8 warps.
// Smem (floats): Bs 512*72 | Wps 64*72 | As 3*(64*68) | bsm 64  = 54592.
// Chunk k (k=0: h2xW', k=1..8: hx cols) lives in As buf k%3 via cp.async.cg,
// issued 2 chunks ahead. gsm epilogue exchange aliases As buf2.
// Inter-CTA sync: monotone release/acquire flag slots (replay-safe).
// ---------------------------------------------------------------------------
#define PS_SMEM_FLOATS 54592   // 218368 bytes
#define AS_STRIDE 68
#define AS_BUF    4352         // 64*68

__global__ void __launch_bounds__(256) lstm_persistent(
    const float* __restrict__ gate_w, const float* __restrict__ wp,
    const float* __restrict__ bp, float* __restrict__ out)
{
    extern __shared__ float sm[];
    float* Bs  = sm;                    // 36864
    float* Wps = sm + 36864;            // 4608
    float* As  = sm + 41472;            // 3*4352 = 13056
    float* bsm = sm + 54528;            // 64
    float* gsm = As + 2 * AS_BUF;       // alias buf2 (4*64*17 = 4352)

    const int tid  = threadIdx.x;
    const int lane = tid & 31, warp = tid >> 5;
    const int g = lane >> 2, tg = lane & 3;
    const int gate = warp & 3;
    const int wm = (warp >> 2) * 32;

    const int ng = blockIdx.x & 31;     // 16 h cols
    const int mt = blockIdx.x >> 5;     // m-tile
    const int m0 = mt * 64;
    const int h0 = ng * 16;

    const float* Wh = gate_w + (size_t)512 * NGATE;
    const uint32_t as_u32 = (uint32_t)__cvta_generic_to_shared(As);

    // monotone flag base (uniform across slots at kernel entry)
    unsigned fbase = *((volatile unsigned*)&g_arrive[mt][ng]);

    // ---- preload weight slices (tf32) + bias ----
    for (int it = tid; it < 8192; it += 256) {        // Wh: 512 k x 16 f4
        int k = it >> 4, c4 = it & 15;
        int gt = c4 >> 2, j4 = c4 & 3;
        float4 v = *(const float4*)(Wh + (size_t)k * NGATE + gt * 512 + h0 + j4 * 4);
        v.x = ftf32(v.x); v.y = ftf32(v.y); v.z = ftf32(v.z); v.w = ftf32(v.w);
        *(float4*)&Bs[k * 72 + gt * 16 + j4 * 4] = v;
    }
    for (int it = tid; it < 1024; it += 256) {        // W': 64 k x 16 f4
        int k = it >> 4, c4 = it & 15;
        int gt = c4 >> 2, j4 = c4 & 3;
        float4 v = *(const float4*)(wp + (size_t)k * NGATE + gt * 512 + h0 + j4 * 4);
        v.x = ftf32(v.x); v.y = ftf32(v.y); v.z = ftf32(v.z); v.w = ftf32(v.w);
        *(float4*)&Wps[k * 72 + gt * 16 + j4 * 4] = v;
    }
    if (tid < 64) {
        int gt = tid >> 4, j = tid & 15;
        bsm[tid] = bp[gt * 512 + h0 + j];
    }
    __syncthreads();

    const float mk = d_mask[gate];
    float cx[4] = {0.f, 0.f, 0.f, 0.f};
    const int um = tid >> 2, uj = (tid & 3) * 4;

    // cp.async issue of one 64x64 chunk into As buffer `buf`
    auto issueA = [&](int buf, const float* src, int ld) {
#pragma unroll
        for (int p = 0; p < 4; p++) {
            int idx = p * 256 + tid;
            int row = idx >> 4, c4 = (idx & 15) << 2;
            cpa16(as_u32 + (uint32_t)(buf * AS_BUF + row * AS_STRIDE + c4) * 4u,
                  src + (size_t)row * ld + c4);
        }
        CP_COMMIT();
    };

    float acc[2][2][4];
    auto compute = [&](const float* Ab, const float* Bp) {
#pragma unroll
        for (int kk = 0; kk < 64; kk += 8) {
            int rb0 = wm + g;
            uint32_t a00 = __float_as_uint(Ab[rb0 * AS_STRIDE + kk + tg]);
            uint32_t a01 = __float_as_uint(Ab[(rb0 + 8) * AS_STRIDE + kk + tg]);
            uint32_t a02 = __float_as_uint(Ab[rb0 * AS_STRIDE + kk + tg + 4]);
            uint32_t a03 = __float_as_uint(Ab[(rb0 + 8) * AS_STRIDE + kk + tg + 4]);
            uint32_t a10 = __float_as_uint(Ab[(rb0 + 16) * AS_STRIDE + kk + tg]);
            uint32_t a11 = __float_as_uint(Ab[(rb0 + 24) * AS_STRIDE + kk + tg]);
            uint32_t a12 = __float_as_uint(Ab[(rb0 + 16) * AS_STRIDE + kk + tg + 4]);
            uint32_t a13 = __float_as_uint(Ab[(rb0 + 24) * AS_STRIDE + kk + tg + 4]);
#pragma unroll
            for (int nf = 0; nf < 2; nf++) {
                uint32_t b0 = __float_as_uint(Bp[(kk + tg) * 72 + gate * 16 + nf * 8 + g]);
                uint32_t b1 = __float_as_uint(Bp[(kk + tg + 4) * 72 + gate * 16 + nf * 8 + g]);
                mma8(acc[0][nf], a00, a01, a02, a03, b0, b1);
                mma8(acc[1][nf], a10, a11, a12, a13, b0, b1);
            }
        }
    };

    // prologue: h2[0] -> buf0
    issueA(0, d_h2 + (size_t)m0 * 64, 64);

    for (int t = 0; t < TT; t++) {
        const float* hx_in  = d_hxbuf[t & 1];
        float*       hx_out = d_hxbuf[(t + 1) & 1];

#pragma unroll
        for (int i = 0; i < 2; i++)
#pragma unroll
            for (int j = 0; j < 2; j++)
#pragma unroll
                for (int e = 0; e < 4; e++) acc[i][j][e] = 0.f;

        CP_WAIT(0);
        __syncthreads();
        compute(As, Wps);                  // chunk 0 (h2 x W'), overlaps barrier

        if (t == 0) {
            __syncthreads();               // all warps done reading buf0
            issueA(0, d_h2 + (size_t)(256 + m0) * 64, 64);   // h2[1]
        } else {
            // wait for step-t hx (flags >= fbase + t), 32 parallel slots
            if (tid < 32) {
                unsigned tgt = fbase + (unsigned)t;
                const unsigned* fp = &g_arrive[mt][tid];
                unsigned v;
                while (true) {
                    asm volatile("ld.acquire.gpu.global.u32 %0, [%1];"
                                 : "=r"(v) : "l"(fp));
                    if ((int)(v - tgt) >= 0) break;
                    __nanosleep(32);
                }
            }
            __syncthreads();
            const float* hxm = hx_in + (size_t)m0 * HHID;
            issueA(1, hxm,      HHID);     // chunk 1
            issueA(2, hxm + 64, HHID);     // chunk 2
#pragma unroll
            for (int c = 1; c <= 8; c++) {
                if (c == 8) {
                    if (t == TT - 1) { CP_WAIT(0); } else { CP_WAIT(1); }
                } else {
                    CP_WAIT(1);
                }
                __syncthreads();
                compute(As + (c % 3) * AS_BUF, Bs + (c - 1) * 4608);
                if (c <= 6) {
                    issueA((c + 2) % 3, hxm + (c + 1) * 64, HHID);
                } else if (c == 7 && t + 1 < TT) {
                    issueA(0, d_h2 + ((size_t)(t + 1) * 256 + m0) * 64, 64);
                }
            }
        }

        __syncthreads();    // As buf2 reads done -> gsm alias safe

        // ---- epilogue: bias + activation*mask -> gsm exchange ----
#pragma unroll
        for (int mf = 0; mf < 2; mf++) {
            int r0 = wm + mf * 16 + g;
#pragma unroll
            for (int nf = 0; nf < 2; nf++) {
                int j0 = nf * 8 + 2 * tg;
                float b0 = bsm[gate * 16 + j0], b1 = bsm[gate * 16 + j0 + 1];
                float p0 = acc[mf][nf][0] + b0;
                float p1 = acc[mf][nf][1] + b1;
                float p2 = acc[mf][nf][2] + b0;
                float p3 = acc[mf][nf][3] + b1;
                float a0, a1, a2, a3;
                if (gate == 2) {
                    a0 = ftanh(p0); a1 = ftanh(p1); a2 = ftanh(p2); a3 = ftanh(p3);
                } else {
                    a0 = fsig(p0); a1 = fsig(p1); a2 = fsig(p2); a3 = fsig(p3);
                }
                float* gp = gsm + gate * 1088;
                gp[r0 * 17 + j0]           = a0 * mk;
                gp[r0 * 17 + j0 + 1]       = a1 * mk;
                gp[(r0 + 8) * 17 + j0]     = a2 * mk;
                gp[(r0 + 8) * 17 + j0 + 1] = a3 * mk;
            }
        }
        __syncthreads();

        // ---- cell update (cx in registers) ----
        float4 h4, c4v, h4r;
        float* hp = &h4.x; float* cp = &c4v.x; float* hr = &h4r.x;
#pragma unroll
        for (int q = 0; q < 4; q++) {
            int jj = uj + q;
            float fv = gsm[0 * 1088 + um * 17 + jj];
            float iv = gsm[1 * 1088 + um * 17 + jj];
            float gv = gsm[2 * 1088 + um * 17 + jj];
            float ov = gsm[3 * 1088 + um * 17 + jj];
            cx[q] = fv * cx[q] + iv * gv;
            cp[q] = cx[q];
            float hn = ov * ftanh(cx[q]);
            hp[q] = hn;
            hr[q] = ftf32(hn);
        }
        int gi = (m0 + um) * HHID + h0 + uj;
        *(float4*)(hx_out + gi) = h4r;                                   // tf32 for recurrence
        *(float4*)(out + ((size_t)t * BBATCH + m0 + um) * HHID + h0 + uj) = h4;
        if (t == TT - 1) {
            *(float4*)(out + STACKED_SZ + gi) = h4;
            *(float4*)(out + STACKED_SZ + STATE_SZ + gi) = c4v;
        }

        __syncthreads();
        if (t < TT - 1 && tid == 0) {
            unsigned nv = fbase + (unsigned)(t + 1);
            asm volatile("st.release.gpu.global.u32 [%0], %1;"
                         :: "l"(&g_arrive[mt][ng]), "r"(nv) : "memory");
        }
    }
}

// ---------------------------------------------------------------------------
extern "C" void kernel_launch(void* const* d_in, const int* in_sizes, int n_in,
                              void* d_out, int out_size)
{
    (void)in_sizes; (void)n_in; (void)out_size;
    const float* inputs = (const float*)d_in[0];
    const float* ew1 = (const float*)d_in[1];
    const float* eb1 = (const float*)d_in[2];
    const float* ew2 = (const float*)d_in[3];
    const float* eb2 = (const float*)d_in[4];
    const float* ew3 = (const float*)d_in[5];
    const float* eb3 = (const float*)d_in[6];
    const float* gw  = (const float*)d_in[7];
    const float* gb  = (const float*)d_in[8];
    const float* sw1 = (const float*)d_in[9];
    const float* sb1 = (const float*)d_in[10];
    const float* sw2 = (const float*)d_in[11];
    const float* sb2 = (const float*)d_in[12];
    float* out = (float*)d_out;

    void *ph1, *ph2, *pwp, *pbp;
    cudaGetSymbolAddress(&ph1, d_h1);
    cudaGetSymbolAddress(&ph2, d_h2);
    cudaGetSymbolAddress(&pwp, d_wp);
    cudaGetSymbolAddress(&pbp, d_bp);

    cudaFuncSetAttribute((const void*)lstm_persistent,
                         cudaFuncAttributeMaxDynamicSharedMemorySize,
                         PS_SMEM_FLOATS * 4);

    mask_kernel<<<1, 32>>>(sw1, sb1, sw2, sb2);
    wprime_kernel<<<32, 256>>>(ew3, gw, (float*)pwp);
    bprime_kernel<<<64, 32>>>(eb3, gw, gb, (float*)pbp);

    dim3 tb(128);
    // h1 = relu(x @ w1 + b1)              [65536,512]x[512,128]
    gemm_tf32_kernel<1, 0><<<dim3(2, MROWS / 64), tb>>>(
        inputs, ew1, eb1, (float*)ph1, MROWS, 128, 512, 128);
    // h2 = tf32(relu(h1 @ w2 + b2))       [65536,128]x[128,64]
    gemm_tf32_kernel<1, 1><<<dim3(1, MROWS / 64), tb>>>(
        (const float*)ph1, ew2, eb2, (float*)ph2, MROWS, 64, 128, 64);

    // persistent fused recurrence
    lstm_persistent<<<128, 256, PS_SMEM_FLOATS * 4>>>(
        gw, (const float*)pwp, (const float*)pbp, out);
}